// round 16
// baseline (speedup 1.0000x reference)
#include <cuda_runtime.h>
#include <math.h>

#define N 1024
#define H 8
#define OBS_LEN 8
#define PRED_LEN 12

// ---------------- scratch (device globals; no allocation) ----------------
__device__ float g_h[N * H];
__device__ float g_c[N * H];
__device__ float g_posA[N * 64];     // posA[i][k] = A[k] . pos_i
__device__ float g_u[N * 64];        // u_i[k], row-major
__device__ float g_v[2][64 * N];     // v_j[k], k-major, j BIT-PERMUTED, double-buffered
__device__ float g_dconst[64];       // d = b1 + W1[:, :32] @ bsp

// j-permutation within each 16-group: j = base + g + 8b  ->  stored at base + 2g + b
__device__ __forceinline__ int permj(int j) {
    return (j & ~15) | (((j & 7) << 1) | ((j >> 3) & 1));
}

__device__ __forceinline__ float sigm(float x) { return 1.f / (1.f + expf(-x)); }

__device__ __forceinline__ unsigned cvt_tf32(float f) {
    unsigned r; asm("cvt.rna.tf32.f32 %0, %1;" : "=r"(r) : "f"(f)); return r;
}

// ---------------- LSTM cell helper ----------------
__device__ __forceinline__ void lstm_step(const float* x, float* h, float* c,
                                          const float* sWih, const float* sWhh,
                                          const float* sb) {
    float gates[32];
    #pragma unroll
    for (int g = 0; g < 32; g++) {
        float a = sb[g];
        #pragma unroll
        for (int m = 0; m < 16; m++) a = fmaf(sWih[g * 16 + m], x[m], a);
        #pragma unroll
        for (int q = 0; q < 8; q++) a = fmaf(sWhh[g * 8 + q], h[q], a);
        gates[g] = a;
    }
    #pragma unroll
    for (int q = 0; q < 8; q++) {
        float ig = sigm(gates[q]);
        float fg = sigm(gates[8 + q]);
        float gg = tanhf(gates[16 + q]);
        float og = sigm(gates[24 + q]);
        float cn = fg * c[q] + ig * gg;
        c[q] = cn;
        h[q] = og * tanhf(cn);
    }
}

// ---------------- encoder: setup + 8 LSTM steps + first decoder LSTM + u/v ----
__global__ void __launch_bounds__(128) k_encoder(
        const float* __restrict__ obs_traj, const float* __restrict__ obs_pos,
        const float* __restrict__ h0, const float* __restrict__ c0,
        const float* __restrict__ We, const float* __restrict__ be,
        const float* __restrict__ WihT, const float* __restrict__ WhhT,
        const float* __restrict__ bihT, const float* __restrict__ bhhT,
        const float* __restrict__ bd,
        const float* __restrict__ WihP, const float* __restrict__ WhhP,
        const float* __restrict__ bihP, const float* __restrict__ bhhP,
        const float* __restrict__ W1, const float* __restrict__ b1,
        const float* __restrict__ Wsp, const float* __restrict__ bsp) {
    __shared__ float sWe[32], sbe[16], sWihT[512], sWhhT[256], sbT[32];
    __shared__ float sWihP[512], sWhhP[256], sbP[32], sbd[16];
    __shared__ float sB[512], sC[512], sA[128], sd[64];
    int tid = threadIdx.x;
    for (int idx = tid; idx < 32; idx += 128) sWe[idx] = We[idx];
    for (int idx = tid; idx < 16; idx += 128) { sbe[idx] = be[idx]; sbd[idx] = bd[idx]; }
    for (int idx = tid; idx < 512; idx += 128) { sWihT[idx] = WihT[idx]; sWihP[idx] = WihP[idx]; }
    for (int idx = tid; idx < 256; idx += 128) { sWhhT[idx] = WhhT[idx]; sWhhP[idx] = WhhP[idx]; }
    for (int idx = tid; idx < 32; idx += 128) { sbT[idx] = bihT[idx] + bhhT[idx];
                                               sbP[idx] = bihP[idx] + bhhP[idx]; }
    for (int idx = tid; idx < 512; idx += 128) {
        int k = idx >> 3, q = idx & 7;
        sB[idx] = W1[k * 48 + 32 + q];   // multiplies h_j -> v
        sC[idx] = W1[k * 48 + 40 + q];   // multiplies h_i -> u
    }
    if (tid < 64) {
        int k = tid;
        float a0 = 0.f, a1 = 0.f, dd = b1[k];
        #pragma unroll 4
        for (int e = 0; e < 32; e++) {
            float w = W1[k * 48 + e];
            a0 = fmaf(w, Wsp[e * 2 + 0], a0);
            a1 = fmaf(w, Wsp[e * 2 + 1], a1);
            dd = fmaf(w, bsp[e], dd);
        }
        sA[k * 2 + 0] = a0; sA[k * 2 + 1] = a1; sd[k] = dd;
        g_dconst[k] = dd;   // same value from every block (benign redundancy)
    }
    __syncthreads();

    int i = blockIdx.x * 128 + tid;

    float h[8], c[8];
    #pragma unroll
    for (int q = 0; q < 8; q++) { h[q] = h0[i * 8 + q]; c[q] = c0[i * 8 + q]; }

    for (int t = 0; t < OBS_LEN; t++) {
        float px = obs_traj[(t * N + i) * 2 + 0];
        float py = obs_traj[(t * N + i) * 2 + 1];
        float x[16];
        #pragma unroll
        for (int m = 0; m < 16; m++)
            x[m] = fmaxf(fmaf(sWe[m * 2 + 0], px, fmaf(sWe[m * 2 + 1], py, sbe[m])), 0.f);
        lstm_step(x, h, c, sWihT, sWhhT, sbT);
    }

    // first decoder step: context=0, output=0 -> x = relu(bd)
    float x[16];
    #pragma unroll
    for (int m = 0; m < 16; m++) x[m] = fmaxf(sbd[m], 0.f);
    #pragma unroll
    for (int q = 0; q < 8; q++) c[q] = 0.f;
    lstm_step(x, h, c, sWihP, sWhhP, sbP);

    #pragma unroll
    for (int q = 0; q < 8; q++) { g_h[i * 8 + q] = h[q]; g_c[i * 8 + q] = c[q]; }

    float qx = obs_pos[((OBS_LEN - 1) * N + i) * 2 + 0];
    float qy = obs_pos[((OBS_LEN - 1) * N + i) * 2 + 1];

    int pj = permj(i);
    #pragma unroll 4
    for (int k = 0; k < 64; k++) {
        float pa = fmaf(sA[k * 2 + 0], qx, sA[k * 2 + 1] * qy);
        g_posA[i * 64 + k] = pa;
        float uu = pa, vv = sd[k] - pa;
        #pragma unroll
        for (int q = 0; q < 8; q++) {
            uu = fmaf(h[q], sC[k * 8 + q], uu);
            vv = fmaf(h[q], sB[k * 8 + q], vv);
        }
        g_u[i * 64 + k] = uu;
        g_v[0][k * N + pj] = vv;
    }
}

// ---------------- pooling via tf32 m16n8k8 mma.sync, 2 accumulator chains ----
// One block per agent i, 8 warps. Warp w covers j in [w*128, (w+1)*128) as
// 8 tiles of 16 j. Per tile: 8 k8-chunks alternating between 2 independent
// accumulator groups (breaks the serial HMMA dependency chain).
__global__ void __launch_bounds__(256, 4) k_pool(
        const int* __restrict__ nei, const float* __restrict__ eps,
        const float* __restrict__ W2, const float* __restrict__ b2,
        const float* __restrict__ Wm, const float* __restrict__ bm,
        const float* __restrict__ Wv, const float* __restrict__ bv,
        const float* __restrict__ Wd, const float* __restrict__ bd,
        const float* __restrict__ WihP, const float* __restrict__ WhhP,
        const float* __restrict__ bihP, const float* __restrict__ bhhP,
        const float* __restrict__ W1,
        float* __restrict__ out, int t) {
    __shared__ float red[64];
    __shared__ float sph[8], spos[2], sx[16], sgate[32], sh[8];

    int i = blockIdx.x;
    int tid = threadIdx.x;
    int w = tid >> 5, lane = tid & 31;
    int g = lane >> 2, tq = lane & 3;

    // B fragments for m16n8k8: chunk cc covers k = 8cc + {tq, tq+4}
    // bfr[2cc] = W2[o=g][8cc+tq], bfr[2cc+1] = W2[o=g][8cc+tq+4]
    unsigned bfr[16];
    #pragma unroll
    for (int cc = 0; cc < 8; cc++) {
        bfr[2 * cc + 0] = cvt_tf32(__ldg(W2 + g * 64 + cc * 8 + tq));
        bfr[2 * cc + 1] = cvt_tf32(__ldg(W2 + g * 64 + cc * 8 + tq + 4));
    }

    // u values: ur[2cc] = u[8cc+tq], ur[2cc+1] = u[8cc+tq+4]
    float ur[16];
    #pragma unroll
    for (int cc = 0; cc < 8; cc++) {
        ur[2 * cc + 0] = __ldg(g_u + i * 64 + cc * 8 + tq);
        ur[2 * cc + 1] = __ldg(g_u + i * 64 + cc * 8 + tq + 4);
    }

    float bb0 = __ldg(b2 + 2 * tq);
    float bb1 = __ldg(b2 + 2 * tq + 1);

    const float* vbuf = g_v[t & 1];
    const int* neirow = nei + (size_t)t * N * N + (size_t)i * N;

    float mx0 = 0.f, mx1 = 0.f;   // running max for o = 2tq, 2tq+1

    #pragma unroll 1
    for (int tile = 0; tile < 8; tile++) {
        int jb = w * 128 + tile * 16;
        int m0 = neirow[jb + g];
        int m1 = neirow[jb + g + 8];
        // two independent accumulator groups (chunk parity)
        float cA0 = 0.f, cA1 = 0.f, cA2 = 0.f, cA3 = 0.f;
        float cB0 = 0.f, cB1 = 0.f, cB2 = 0.f, cB3 = 0.f;
        const float* vrow = vbuf + jb + 2 * g;    // + k*N per k
        #pragma unroll
        for (int cc = 0; cc < 8; cc++) {
            float2 v0 = *(const float2*)(vrow + (size_t)(8 * cc + tq) * N);
            float2 v1 = *(const float2*)(vrow + (size_t)(8 * cc + tq + 4) * N);
            float u0 = ur[2 * cc + 0], u1 = ur[2 * cc + 1];
            unsigned a0 = __float_as_uint(fmaxf(u0 + v0.x, 0.f));
            unsigned a1 = __float_as_uint(fmaxf(u0 + v0.y, 0.f));
            unsigned a2 = __float_as_uint(fmaxf(u1 + v1.x, 0.f));
            unsigned a3 = __float_as_uint(fmaxf(u1 + v1.y, 0.f));
            if (cc & 1) {
                asm("mma.sync.aligned.m16n8k8.row.col.f32.tf32.tf32.f32 "
                    "{%0,%1,%2,%3}, {%4,%5,%6,%7}, {%8,%9}, {%0,%1,%2,%3};"
                    : "+f"(cB0), "+f"(cB1), "+f"(cB2), "+f"(cB3)
                    : "r"(a0), "r"(a1), "r"(a2), "r"(a3),
                      "r"(bfr[2 * cc]), "r"(bfr[2 * cc + 1]));
            } else {
                asm("mma.sync.aligned.m16n8k8.row.col.f32.tf32.tf32.f32 "
                    "{%0,%1,%2,%3}, {%4,%5,%6,%7}, {%8,%9}, {%0,%1,%2,%3};"
                    : "+f"(cA0), "+f"(cA1), "+f"(cA2), "+f"(cA3)
                    : "r"(a0), "r"(a1), "r"(a2), "r"(a3),
                      "r"(bfr[2 * cc]), "r"(bfr[2 * cc + 1]));
            }
        }
        float p0 = cA0 + cB0 + bb0, p1 = cA1 + cB1 + bb1;
        float p2 = cA2 + cB2 + bb0, p3 = cA3 + cB3 + bb1;
        if (m0 > 0) { mx0 = fmaxf(mx0, fmaxf(p0, 0.f)); mx1 = fmaxf(mx1, fmaxf(p1, 0.f)); }
        if (m1 > 0) { mx0 = fmaxf(mx0, fmaxf(p2, 0.f)); mx1 = fmaxf(mx1, fmaxf(p3, 0.f)); }
    }

    // reduce over g-lanes (j) within warp; tq-lanes hold distinct o-pairs
    #pragma unroll
    for (int off = 4; off <= 16; off <<= 1) {
        mx0 = fmaxf(mx0, __shfl_xor_sync(0xffffffffu, mx0, off));
        mx1 = fmaxf(mx1, __shfl_xor_sync(0xffffffffu, mx1, off));
    }
    if (g == 0) { red[w * 8 + 2 * tq] = mx0; red[w * 8 + 2 * tq + 1] = mx1; }
    __syncthreads();

    // ---- warp 0 only from here ----
    if (tid >= 32) return;
    int l = lane;

    if (l < 8) {
        float m0 = red[l];
        #pragma unroll
        for (int ww = 1; ww < 8; ww++) m0 = fmaxf(m0, red[ww * 8 + l]);
        sph[l] = m0;
    }
    __syncwarp();

    // heads: lanes 0,1
    if (l < 2) {
        int r = l;
        float mu = bm[r], lv = bv[r];
        #pragma unroll
        for (int q = 0; q < 4; q++) {
            mu = fmaf(Wm[r * 12 + q], g_h[i * 8 + q], mu);
            lv = fmaf(Wv[r * 12 + q], g_h[i * 8 + 4 + q], lv);
        }
        #pragma unroll
        for (int q = 0; q < 8; q++) {
            mu = fmaf(Wm[r * 12 + 4 + q], sph[q], mu);
            lv = fmaf(Wv[r * 12 + 4 + q], sph[q], lv);
        }
        float e = eps[(t * N + i) * 2 + r];
        float pos = mu + e * expf(0.5f * lv);
        int base = (t * N + i) * 2 + r;
        out[base] = pos;
        out[PRED_LEN * N * 2 + base] = mu;
        out[2 * PRED_LEN * N * 2 + base] = lv;
        spos[r] = pos;
    }
    if (t == PRED_LEN - 1) return;
    __syncwarp();

    // decoder input layer: lanes 0-15
    if (l < 16) {
        int m = l;
        float a = bd[m];
        #pragma unroll
        for (int q = 0; q < 8; q++) a = fmaf(Wd[m * 10 + q], sph[q], a);
        a = fmaf(Wd[m * 10 + 8], spos[0], a);
        a = fmaf(Wd[m * 10 + 9], spos[1], a);
        sx[m] = fmaxf(a, 0.f);
    }
    __syncwarp();

    // gates: all 32 lanes
    {
        int gg = l;
        float a = bihP[gg] + bhhP[gg];
        #pragma unroll
        for (int m = 0; m < 16; m++) a = fmaf(WihP[gg * 16 + m], sx[m], a);
        #pragma unroll
        for (int q = 0; q < 8; q++) a = fmaf(WhhP[gg * 8 + q], g_h[i * 8 + q], a);
        sgate[gg] = a;
    }
    __syncwarp();

    // cell update: lanes 0-7
    if (l < 8) {
        int q = l;
        float ig = sigm(sgate[q]);
        float fg = sigm(sgate[8 + q]);
        float gg = tanhf(sgate[16 + q]);
        float og = sigm(sgate[24 + q]);
        float cn = fg * g_c[i * 8 + q] + ig * gg;
        float hn = og * tanhf(cn);
        g_c[i * 8 + q] = cn;
        g_h[i * 8 + q] = hn;
        sh[q] = hn;
    }
    __syncwarp();

    // u/v update: 32 lanes, 2 k each
    {
        float hreg[8];
        #pragma unroll
        for (int q = 0; q < 8; q++) hreg[q] = sh[q];
        int pj = permj(i);
        #pragma unroll
        for (int s = 0; s < 2; s++) {
            int k = l * 2 + s;
            float pa = g_posA[i * 64 + k];
            float uu = pa, vv = g_dconst[k] - pa;
            #pragma unroll
            for (int q = 0; q < 8; q++) {
                uu = fmaf(hreg[q], W1[k * 48 + 40 + q], uu);
                vv = fmaf(hreg[q], W1[k * 48 + 32 + q], vv);
            }
            g_u[i * 64 + k] = uu;
            g_v[(t + 1) & 1][k * N + pj] = vv;
        }
    }
}

// ---------------- launch ----------------
extern "C" void kernel_launch(void* const* d_in, const int* in_sizes, int n_in,
                              void* d_out, int out_size) {
    const float* obs_traj     = (const float*)d_in[0];
    const float* obs_traj_obs = (const float*)d_in[1];
    const int*   nei_index    = (const int*)d_in[2];
    const float* h0   = (const float*)d_in[4];
    const float* c0   = (const float*)d_in[5];
    const float* eps  = (const float*)d_in[6];
    const float* We   = (const float*)d_in[7];
    const float* be   = (const float*)d_in[8];
    const float* Wih_t = (const float*)d_in[9];
    const float* Whh_t = (const float*)d_in[10];
    const float* bih_t = (const float*)d_in[11];
    const float* bhh_t = (const float*)d_in[12];
    const float* Wd   = (const float*)d_in[13];
    const float* bd   = (const float*)d_in[14];
    const float* Wih_p = (const float*)d_in[15];
    const float* Whh_p = (const float*)d_in[16];
    const float* bih_p = (const float*)d_in[17];
    const float* bhh_p = (const float*)d_in[18];
    const float* Wsp  = (const float*)d_in[19];
    const float* bsp  = (const float*)d_in[20];
    const float* W1   = (const float*)d_in[21];
    const float* b1   = (const float*)d_in[22];
    const float* W2   = (const float*)d_in[23];
    const float* b2   = (const float*)d_in[24];
    const float* Wm   = (const float*)d_in[25];
    const float* bm   = (const float*)d_in[26];
    const float* Wv   = (const float*)d_in[27];
    const float* bv   = (const float*)d_in[28];
    float* out = (float*)d_out;

    k_encoder<<<N / 128, 128>>>(obs_traj, obs_traj_obs, h0, c0, We, be,
                                Wih_t, Whh_t, bih_t, bhh_t, bd,
                                Wih_p, Whh_p, bih_p, bhh_p, W1, b1, Wsp, bsp);
    for (int t = 0; t < PRED_LEN; t++) {
        k_pool<<<N, 256>>>(nei_index, eps, W2, b2, Wm, bm, Wv, bv,
                           Wd, bd, Wih_p, Whh_p, bih_p, bhh_p, W1, out, t);
    }
}

// round 17
// speedup vs baseline: 1.4411x; 1.4411x over previous
#include <cuda_runtime.h>
#include <math.h>

#define N 1024
#define H 8
#define OBS_LEN 8
#define PRED_LEN 12

// ---------------- scratch (device globals; no allocation) ----------------
__device__ float g_h[N * H];
__device__ float g_c[N * H];
__device__ float g_posA[N * 64];     // posA[i][k] = A[k] . pos_i
__device__ float g_u[N * 64];        // u_i[k], row-major
__device__ float g_v[2][64 * N];     // v, COALESCED MMA layout (see vaddr), double-buffered
__device__ float g_dconst[64];       // d = b1 + W1[:, :32] @ bsp

// Coalesced v layout: warp chunk reads become 256B contiguous.
// addr(k,j) = (k>>2)*4096 + ((j>>4)*8 + (j&7))*8 + (k&3)*2 + ((j>>3)&1)
__device__ __forceinline__ int vaddr(int k, int j) {
    return ((k >> 2) << 12) | ((((j >> 4) << 3) | (j & 7)) << 3) | ((k & 3) << 1) | ((j >> 3) & 1);
}

__device__ __forceinline__ float sigm(float x) { return 1.f / (1.f + expf(-x)); }

__device__ __forceinline__ unsigned cvt_tf32(float f) {
    unsigned r; asm("cvt.rna.tf32.f32 %0, %1;" : "=r"(r) : "f"(f)); return r;
}

// ---------------- LSTM cell helper ----------------
__device__ __forceinline__ void lstm_step(const float* x, float* h, float* c,
                                          const float* sWih, const float* sWhh,
                                          const float* sb) {
    float gates[32];
    #pragma unroll
    for (int g = 0; g < 32; g++) {
        float a = sb[g];
        #pragma unroll
        for (int m = 0; m < 16; m++) a = fmaf(sWih[g * 16 + m], x[m], a);
        #pragma unroll
        for (int q = 0; q < 8; q++) a = fmaf(sWhh[g * 8 + q], h[q], a);
        gates[g] = a;
    }
    #pragma unroll
    for (int q = 0; q < 8; q++) {
        float ig = sigm(gates[q]);
        float fg = sigm(gates[8 + q]);
        float gg = tanhf(gates[16 + q]);
        float og = sigm(gates[24 + q]);
        float cn = fg * c[q] + ig * gg;
        c[q] = cn;
        h[q] = og * tanhf(cn);
    }
}

// ---------------- encoder: setup + 8 LSTM steps + first decoder LSTM + u/v ----
__global__ void __launch_bounds__(128) k_encoder(
        const float* __restrict__ obs_traj, const float* __restrict__ obs_pos,
        const float* __restrict__ h0, const float* __restrict__ c0,
        const float* __restrict__ We, const float* __restrict__ be,
        const float* __restrict__ WihT, const float* __restrict__ WhhT,
        const float* __restrict__ bihT, const float* __restrict__ bhhT,
        const float* __restrict__ bd,
        const float* __restrict__ WihP, const float* __restrict__ WhhP,
        const float* __restrict__ bihP, const float* __restrict__ bhhP,
        const float* __restrict__ W1, const float* __restrict__ b1,
        const float* __restrict__ Wsp, const float* __restrict__ bsp) {
    __shared__ float sWe[32], sbe[16], sWihT[512], sWhhT[256], sbT[32];
    __shared__ float sWihP[512], sWhhP[256], sbP[32], sbd[16];
    __shared__ float sB[512], sC[512], sA[128], sd[64];
    int tid = threadIdx.x;
    for (int idx = tid; idx < 32; idx += 128) sWe[idx] = We[idx];
    for (int idx = tid; idx < 16; idx += 128) { sbe[idx] = be[idx]; sbd[idx] = bd[idx]; }
    for (int idx = tid; idx < 512; idx += 128) { sWihT[idx] = WihT[idx]; sWihP[idx] = WihP[idx]; }
    for (int idx = tid; idx < 256; idx += 128) { sWhhT[idx] = WhhT[idx]; sWhhP[idx] = WhhP[idx]; }
    for (int idx = tid; idx < 32; idx += 128) { sbT[idx] = bihT[idx] + bhhT[idx];
                                               sbP[idx] = bihP[idx] + bhhP[idx]; }
    for (int idx = tid; idx < 512; idx += 128) {
        int k = idx >> 3, q = idx & 7;
        sB[idx] = W1[k * 48 + 32 + q];   // multiplies h_j -> v
        sC[idx] = W1[k * 48 + 40 + q];   // multiplies h_i -> u
    }
    if (tid < 64) {
        int k = tid;
        float a0 = 0.f, a1 = 0.f, dd = b1[k];
        #pragma unroll 4
        for (int e = 0; e < 32; e++) {
            float w = W1[k * 48 + e];
            a0 = fmaf(w, Wsp[e * 2 + 0], a0);
            a1 = fmaf(w, Wsp[e * 2 + 1], a1);
            dd = fmaf(w, bsp[e], dd);
        }
        sA[k * 2 + 0] = a0; sA[k * 2 + 1] = a1; sd[k] = dd;
        g_dconst[k] = dd;   // same value from every block (benign redundancy)
    }
    __syncthreads();

    int i = blockIdx.x * 128 + tid;

    float h[8], c[8];
    #pragma unroll
    for (int q = 0; q < 8; q++) { h[q] = h0[i * 8 + q]; c[q] = c0[i * 8 + q]; }

    for (int t = 0; t < OBS_LEN; t++) {
        float px = obs_traj[(t * N + i) * 2 + 0];
        float py = obs_traj[(t * N + i) * 2 + 1];
        float x[16];
        #pragma unroll
        for (int m = 0; m < 16; m++)
            x[m] = fmaxf(fmaf(sWe[m * 2 + 0], px, fmaf(sWe[m * 2 + 1], py, sbe[m])), 0.f);
        lstm_step(x, h, c, sWihT, sWhhT, sbT);
    }

    // first decoder step: context=0, output=0 -> x = relu(bd)
    float x[16];
    #pragma unroll
    for (int m = 0; m < 16; m++) x[m] = fmaxf(sbd[m], 0.f);
    #pragma unroll
    for (int q = 0; q < 8; q++) c[q] = 0.f;
    lstm_step(x, h, c, sWihP, sWhhP, sbP);

    #pragma unroll
    for (int q = 0; q < 8; q++) { g_h[i * 8 + q] = h[q]; g_c[i * 8 + q] = c[q]; }

    float qx = obs_pos[((OBS_LEN - 1) * N + i) * 2 + 0];
    float qy = obs_pos[((OBS_LEN - 1) * N + i) * 2 + 1];

    #pragma unroll 4
    for (int k = 0; k < 64; k++) {
        float pa = fmaf(sA[k * 2 + 0], qx, sA[k * 2 + 1] * qy);
        g_posA[i * 64 + k] = pa;
        float uu = pa, vv = sd[k] - pa;
        #pragma unroll
        for (int q = 0; q < 8; q++) {
            uu = fmaf(h[q], sC[k * 8 + q], uu);
            vv = fmaf(h[q], sB[k * 8 + q], vv);
        }
        g_u[i * 64 + k] = uu;
        g_v[0][vaddr(k, i)] = vv;
    }
}

// ---------------- pooling via tf32 m16n8k4 mma.sync, coalesced v -------------
// One block per agent i, 8 warps. Warp w covers j in [w*128, (w+1)*128) as
// 8 tiles of 16 j. Per tile: batch-load 16 float2 (each LDG.64 warp-access is
// 256B contiguous in the new layout), then 16 chained MMAs.
__global__ void __launch_bounds__(256, 3) k_pool(
        const int* __restrict__ nei, const float* __restrict__ eps,
        const float* __restrict__ W2, const float* __restrict__ b2,
        const float* __restrict__ Wm, const float* __restrict__ bm,
        const float* __restrict__ Wv, const float* __restrict__ bv,
        const float* __restrict__ Wd, const float* __restrict__ bd,
        const float* __restrict__ WihP, const float* __restrict__ WhhP,
        const float* __restrict__ bihP, const float* __restrict__ bhhP,
        const float* __restrict__ W1,
        float* __restrict__ out, int t) {
    __shared__ float red[64];
    __shared__ float sph[8], spos[2], sx[16], sgate[32], sh[8];

    int i = blockIdx.x;
    int tid = threadIdx.x;
    int w = tid >> 5, lane = tid & 31;
    int g = lane >> 2, tq = lane & 3;

    // B fragments: B[k=4cc+tq][n=g] = W2[o=g][k], one-time RNA conversion
    unsigned bfr[16];
    #pragma unroll
    for (int cc = 0; cc < 16; cc++)
        bfr[cc] = cvt_tf32(__ldg(W2 + g * 64 + cc * 4 + tq));

    // u values this thread needs: u[4cc + tq]
    float ur[16];
    #pragma unroll
    for (int cc = 0; cc < 16; cc++)
        ur[cc] = __ldg(g_u + i * 64 + cc * 4 + tq);

    float bb0 = __ldg(b2 + 2 * tq);
    float bb1 = __ldg(b2 + 2 * tq + 1);

    const float* vbuf = g_v[t & 1];
    const int* neirow = nei + (size_t)t * N * N + (size_t)i * N;

    float mx0 = 0.f, mx1 = 0.f;   // running max for o = 2tq, 2tq+1

    #pragma unroll 1
    for (int tile = 0; tile < 8; tile++) {
        int jb = w * 128 + tile * 16;
        int m0 = neirow[jb + g];
        int m1 = neirow[jb + g + 8];
        // this thread's chunk-cc load: float-offset cc*4096 + ((jb>>4)*8+g)*8 + tq*2
        const float2* vbase = (const float2*)(vbuf + ((((jb >> 4) << 3) | g) << 3) + (tq << 1));
        float2 vvv[16];
        #pragma unroll
        for (int cc = 0; cc < 16; cc++)
            vvv[cc] = vbase[cc * 2048];   // 4096 floats = 2048 float2 per k-group
        float c0 = 0.f, c1 = 0.f, c2 = 0.f, c3 = 0.f;
        #pragma unroll
        for (int cc = 0; cc < 16; cc++) {
            float z0 = fmaxf(ur[cc] + vvv[cc].x, 0.f);
            float z1 = fmaxf(ur[cc] + vvv[cc].y, 0.f);
            unsigned a0 = __float_as_uint(z0);   // raw bits; HMMA truncates to tf32
            unsigned a1 = __float_as_uint(z1);
            asm("mma.sync.aligned.m16n8k4.row.col.f32.tf32.tf32.f32 "
                "{%0,%1,%2,%3}, {%4,%5}, {%6}, {%0,%1,%2,%3};"
                : "+f"(c0), "+f"(c1), "+f"(c2), "+f"(c3)
                : "r"(a0), "r"(a1), "r"(bfr[cc]));
        }
        float p0 = c0 + bb0, p1 = c1 + bb1, p2 = c2 + bb0, p3 = c3 + bb1;
        if (m0 > 0) { mx0 = fmaxf(mx0, fmaxf(p0, 0.f)); mx1 = fmaxf(mx1, fmaxf(p1, 0.f)); }
        if (m1 > 0) { mx0 = fmaxf(mx0, fmaxf(p2, 0.f)); mx1 = fmaxf(mx1, fmaxf(p3, 0.f)); }
    }

    // reduce over g-lanes (j) within warp; tq-lanes hold distinct o-pairs
    #pragma unroll
    for (int off = 4; off <= 16; off <<= 1) {
        mx0 = fmaxf(mx0, __shfl_xor_sync(0xffffffffu, mx0, off));
        mx1 = fmaxf(mx1, __shfl_xor_sync(0xffffffffu, mx1, off));
    }
    if (g == 0) { red[w * 8 + 2 * tq] = mx0; red[w * 8 + 2 * tq + 1] = mx1; }
    __syncthreads();

    // ---- warp 0 only from here ----
    if (tid >= 32) return;
    int l = lane;

    if (l < 8) {
        float m0 = red[l];
        #pragma unroll
        for (int ww = 1; ww < 8; ww++) m0 = fmaxf(m0, red[ww * 8 + l]);
        sph[l] = m0;
    }
    __syncwarp();

    // heads: lanes 0,1
    if (l < 2) {
        int r = l;
        float mu = bm[r], lv = bv[r];
        #pragma unroll
        for (int q = 0; q < 4; q++) {
            mu = fmaf(Wm[r * 12 + q], g_h[i * 8 + q], mu);
            lv = fmaf(Wv[r * 12 + q], g_h[i * 8 + 4 + q], lv);
        }
        #pragma unroll
        for (int q = 0; q < 8; q++) {
            mu = fmaf(Wm[r * 12 + 4 + q], sph[q], mu);
            lv = fmaf(Wv[r * 12 + 4 + q], sph[q], lv);
        }
        float e = eps[(t * N + i) * 2 + r];
        float pos = mu + e * expf(0.5f * lv);
        int base = (t * N + i) * 2 + r;
        out[base] = pos;
        out[PRED_LEN * N * 2 + base] = mu;
        out[2 * PRED_LEN * N * 2 + base] = lv;
        spos[r] = pos;
    }
    if (t == PRED_LEN - 1) return;
    __syncwarp();

    // decoder input layer: lanes 0-15
    if (l < 16) {
        int m = l;
        float a = bd[m];
        #pragma unroll
        for (int q = 0; q < 8; q++) a = fmaf(Wd[m * 10 + q], sph[q], a);
        a = fmaf(Wd[m * 10 + 8], spos[0], a);
        a = fmaf(Wd[m * 10 + 9], spos[1], a);
        sx[m] = fmaxf(a, 0.f);
    }
    __syncwarp();

    // gates: all 32 lanes
    {
        int gg = l;
        float a = bihP[gg] + bhhP[gg];
        #pragma unroll
        for (int m = 0; m < 16; m++) a = fmaf(WihP[gg * 16 + m], sx[m], a);
        #pragma unroll
        for (int q = 0; q < 8; q++) a = fmaf(WhhP[gg * 8 + q], g_h[i * 8 + q], a);
        sgate[gg] = a;
    }
    __syncwarp();

    // cell update: lanes 0-7
    if (l < 8) {
        int q = l;
        float ig = sigm(sgate[q]);
        float fg = sigm(sgate[8 + q]);
        float gg = tanhf(sgate[16 + q]);
        float og = sigm(sgate[24 + q]);
        float cn = fg * g_c[i * 8 + q] + ig * gg;
        float hn = og * tanhf(cn);
        g_c[i * 8 + q] = cn;
        g_h[i * 8 + q] = hn;
        sh[q] = hn;
    }
    __syncwarp();

    // u/v update: 32 lanes, 2 k each
    {
        float hreg[8];
        #pragma unroll
        for (int q = 0; q < 8; q++) hreg[q] = sh[q];
        #pragma unroll
        for (int s = 0; s < 2; s++) {
            int k = l * 2 + s;
            float pa = g_posA[i * 64 + k];
            float uu = pa, vv = g_dconst[k] - pa;
            #pragma unroll
            for (int q = 0; q < 8; q++) {
                uu = fmaf(hreg[q], W1[k * 48 + 40 + q], uu);
                vv = fmaf(hreg[q], W1[k * 48 + 32 + q], vv);
            }
            g_u[i * 64 + k] = uu;
            g_v[(t + 1) & 1][vaddr(k, i)] = vv;
        }
    }
}

// ---------------- launch ----------------
extern "C" void kernel_launch(void* const* d_in, const int* in_sizes, int n_in,
                              void* d_out, int out_size) {
    const float* obs_traj     = (const float*)d_in[0];
    const float* obs_traj_obs = (const float*)d_in[1];
    const int*   nei_index    = (const int*)d_in[2];
    const float* h0   = (const float*)d_in[4];
    const float* c0   = (const float*)d_in[5];
    const float* eps  = (const float*)d_in[6];
    const float* We   = (const float*)d_in[7];
    const float* be   = (const float*)d_in[8];
    const float* Wih_t = (const float*)d_in[9];
    const float* Whh_t = (const float*)d_in[10];
    const float* bih_t = (const float*)d_in[11];
    const float* bhh_t = (const float*)d_in[12];
    const float* Wd   = (const float*)d_in[13];
    const float* bd   = (const float*)d_in[14];
    const float* Wih_p = (const float*)d_in[15];
    const float* Whh_p = (const float*)d_in[16];
    const float* bih_p = (const float*)d_in[17];
    const float* bhh_p = (const float*)d_in[18];
    const float* Wsp  = (const float*)d_in[19];
    const float* bsp  = (const float*)d_in[20];
    const float* W1   = (const float*)d_in[21];
    const float* b1   = (const float*)d_in[22];
    const float* W2   = (const float*)d_in[23];
    const float* b2   = (const float*)d_in[24];
    const float* Wm   = (const float*)d_in[25];
    const float* bm   = (const float*)d_in[26];
    const float* Wv   = (const float*)d_in[27];
    const float* bv   = (const float*)d_in[28];
    float* out = (float*)d_out;

    k_encoder<<<N / 128, 128>>>(obs_traj, obs_traj_obs, h0, c0, We, be,
                                Wih_t, Whh_t, bih_t, bhh_t, bd,
                                Wih_p, Whh_p, bih_p, bhh_p, W1, b1, Wsp, bsp);
    for (int t = 0; t < PRED_LEN; t++) {
        k_pool<<<N, 256>>>(nei_index, eps, W2, b2, Wm, bm, Wv, bv,
                           Wd, bd, Wih_p, Whh_p, bih_p, bhh_p, W1, out, t);
    }
}